// round 2
// baseline (speedup 1.0000x reference)
#include <cuda_runtime.h>
#include <math.h>

#define NUM_BINS 36
#define WARPS_PER_BLOCK 8
#define PATCH 32
#define HSLOT (NUM_BINS * 32)      // 1152 floats: hist[36][32]
#define WSTRIDE 1232               // hist + raw(36->40) + smoothed(36->40)

__device__ float d_w[32];          // 1D gaussian weighting (outer-product factor)
__device__ float d_sk[5];          // discrete gaussian smoothing kernel

// ---------------------------------------------------------------------------
// Init kernel: reproduce the reference's float64 constant computation exactly.
// ---------------------------------------------------------------------------
__global__ void init_consts_kernel() {
    __shared__ double g[32];
    int t = threadIdx.x;
    if (t < 32) {
        double sigma = 32.0 / 6.0;
        double x = (double)t - 16.0 + 0.5;   // even ksize -> +0.5
        g[t] = exp(-x * x / (2.0 * sigma * sigma));
    }
    __syncthreads();
    if (t == 0) {
        double s = 0.0;
        for (int i = 0; i < 32; i++) s += g[i];
        for (int i = 0; i < 32; i++) d_w[i] = (float)(g[i] / s);

        // discrete gaussian kernel, sigma=1.6, ksize=5
        double tt = 1.6 * 1.6;
        double iv[3];
        for (int n = 0; n < 3; n++) {
            double sum = 0.0;
            for (int k = 0; k < 40; k++) {
                double num = pow(tt * 0.5, (double)(2 * k + n));
                double fk = 1.0, fkn = 1.0;
                for (int i = 2; i <= k; i++) fk *= (double)i;
                for (int i = 2; i <= k + n; i++) fkn *= (double)i;
                sum += num / (fk * fkn);
            }
            iv[n] = sum;
        }
        double e = exp(-tt);
        double vals[5] = { e * iv[2], e * iv[1], e * iv[0], e * iv[1], e * iv[2] };
        double s2 = vals[0] + vals[1] + vals[2] + vals[3] + vals[4];
        for (int j = 0; j < 5; j++) d_sk[j] = (float)(vals[j] / s2);
    }
}

// ---------------------------------------------------------------------------
// atan2, ~1 ulp: 1 fast-div + 9 FMA minimax poly (SLEEF-style coefficients).
// ---------------------------------------------------------------------------
__device__ __forceinline__ float fast_atan2f(float y, float x) {
    float ax = fabsf(x), ay = fabsf(y);
    float mx = fmaxf(ax, ay);
    float mn = fminf(ax, ay);
    float t = __fdividef(mn, mx);
    float s = t * t;
    float p =            0.00282363896258175373077393f;
    p = fmaf(p, s,      -0.0159569028764963150024414f);
    p = fmaf(p, s,       0.0425049886107444763183594f);
    p = fmaf(p, s,      -0.0748900920152664184570312f);
    p = fmaf(p, s,       0.106347933411598205566406f);
    p = fmaf(p, s,      -0.142027363181114196777344f);
    p = fmaf(p, s,       0.199926957488059997558594f);
    p = fmaf(p, s,      -0.333331018686294555664062f);
    float a = fmaf(p * s, t, t);
    if (ay > ax)  a = 1.5707963267948966f - a;
    if (x < 0.0f) a = 3.1415926535897931f - a;
    return copysignf(a, y);
}

// ---------------------------------------------------------------------------
// Main kernel: one warp per patch.
//  - patch column per lane, rows in registers; Sobel via shfl of column sums
//  - per-lane histogram columns in smem (bank-conflict-free, atomic-free)
//  - warp-level reduce + smooth (all 36 bins) + argmax + parabola fit
// ---------------------------------------------------------------------------
__global__ void __launch_bounds__(WARPS_PER_BLOCK * 32)
patch_orient_kernel(const float* __restrict__ in, float* __restrict__ out) {
    __shared__ float hist[WARPS_PER_BLOCK * WSTRIDE];
    __shared__ float sW[32];
    __shared__ float sK[8];

    const unsigned FULL = 0xffffffffu;
    int tid = threadIdx.x;
    if (tid < 32) sW[tid] = d_w[tid];
    if (tid >= 32 && tid < 37) sK[tid - 32] = d_sk[tid - 32];
    __syncthreads();

    int warp = tid >> 5;
    int lane = tid & 31;
    int patch = blockIdx.x * WARPS_PER_BLOCK + warp;

    const float* src = in + (size_t)patch * (PATCH * PATCH) + lane;
    float p[PATCH];
#pragma unroll
    for (int r = 0; r < PATCH; r++) p[r] = src[r * PATCH];

    float* h = hist + warp * WSTRIDE;
#pragma unroll
    for (int b = 0; b < NUM_BINS; b++) h[b * 32 + lane] = 0.0f;

    const float wc = sW[lane];
    const int lm1 = (lane == 0) ? 0 : lane - 1;
    const int lp1 = (lane == 31) ? 31 : lane + 1;

#pragma unroll
    for (int r = 0; r < PATCH; r++) {
        float pm = p[(r == 0) ? 0 : r - 1];
        float pp = p[(r == PATCH - 1) ? PATCH - 1 : r + 1];
        float srow = fmaf(2.0f, p[r], pm + pp);   // 1-2-1 column sum (for gx)
        float d    = pp - pm;                     // row diff (for gy)

        float sl = __shfl_sync(FULL, srow, lm1);
        float sr = __shfl_sync(FULL, srow, lp1);
        float dl = __shfl_sync(FULL, d, lm1);
        float dr = __shfl_sync(FULL, d, lp1);

        float gx = (sr - sl) * 0.125f;
        float gy = fmaf(2.0f, d, dl + dr) * 0.125f;

        float m2  = fmaf(gx, gx, fmaf(gy, gy, 1e-8f));
        float mag = m2 * rsqrtf(m2) * (sW[r] * wc);

        float at = fast_atan2f(gy, gx + 1e-8f);
        // o = 36*(at + 3*pi)/(2*pi) = at * (18/pi) + 54,  o in (36, 72]
        float o  = fmaf(at, 5.7295779513082320877f, 54.0f);
        float fo = floorf(o);
        float wo1 = o - fo;
        int i0 = (int)fo - 36;
        if (i0 < 0) i0 += 36;            // guards for o at/near range ends
        if (i0 >= 36) i0 -= 36;
        int i1 = i0 + 1;
        if (i1 == 36) i1 = 0;

        float w1v = wo1 * mag;
        float w0v = mag - w1v;
        h[i0 * 32 + lane] += w0v;        // bank == lane: conflict-free
        h[i1 * 32 + lane] += w1v;
    }
    __syncwarp();

    // Reduce 36 bins x 32 lane-slots. Lane l sums bin l; lanes 0-3 also bins 32-35.
    float acc = 0.0f, acc2 = 0.0f;
#pragma unroll
    for (int k = 0; k < 32; k++) {
        int kk = (k + lane) & 31;                    // rotate -> bank-conflict-free
        acc += h[lane * 32 + kk];
        if (lane < 4) acc2 += h[(32 + lane) * 32 + kk];
    }
    float* red  = h + HSLOT;        // 36 raw bins
    float* red2 = red + 40;         // 36 smoothed bins
    red[lane] = acc;
    if (lane < 4) red[32 + lane] = acc2;
    __syncwarp();

    // Smooth all 36 bins with wrap-padded 5-tap kernel.
    // Lane l computes bin l; lanes 0-3 additionally compute bins 32-35.
    float k0 = sK[0], k1 = sK[1], k2 = sK[2], k3 = sK[3], k4 = sK[4];
    float sv = k0 * red[(lane + 34) % 36]
             + k1 * red[(lane + 35) % 36]
             + k2 * red[lane]
             + k3 * red[(lane + 1) % 36]
             + k4 * red[(lane + 2) % 36];
    red2[lane] = sv;
    float sv2 = -1e30f;
    if (lane < 4) {
        int b = 32 + lane;
        sv2 = k0 * red[(b + 34) % 36]
            + k1 * red[(b + 35) % 36]
            + k2 * red[b]
            + k3 * red[(b + 1) % 36]
            + k4 * red[(b + 2) % 36];
        red2[b] = sv2;
    }
    __syncwarp();

    // Per-lane candidate: bin `lane`, optionally replaced by bin `32+lane`
    // (strict > keeps lowest-index-wins tie semantics since 32+lane > lane).
    float v = sv;
    int idx = lane;
    if (lane < 4 && sv2 > v) { v = sv2; idx = 32 + lane; }

    // Warp argmax (lowest index on ties, matching jnp.argmax).
#pragma unroll
    for (int off = 16; off; off >>= 1) {
        float v2 = __shfl_xor_sync(FULL, v, off);
        int   i2 = __shfl_xor_sync(FULL, idx, off);
        if (v2 > v || (v2 == v && i2 < idx)) { v = v2; idx = i2; }
    }

    if (lane == 0) {
        float left  = red2[(idx + 35) % 36];
        float right = red2[(idx + 1) % 36];
        float denom = left + right - 2.0f * v;
        float c = 0.5f * (left - right) / denom;
        // angle = pi - (idx + c) * 2*pi/36   (the /HW scale cancels everywhere)
        float angle = 3.14159265358979f - ((float)idx + c) * 0.17453292519943295f;
        out[patch] = angle;
    }
}

// ---------------------------------------------------------------------------
extern "C" void kernel_launch(void* const* d_in, const int* in_sizes, int n_in,
                              void* d_out, int out_size) {
    const float* patch = (const float*)d_in[0];
    float* out = (float*)d_out;
    int n_patches = in_sizes[0] / (PATCH * PATCH);   // 32768

    init_consts_kernel<<<1, 64>>>();
    int blocks = n_patches / WARPS_PER_BLOCK;        // 4096
    patch_orient_kernel<<<blocks, WARPS_PER_BLOCK * 32>>>(patch, out);
}

// round 3
// speedup vs baseline: 7.9221x; 7.9221x over previous
#include <cuda_runtime.h>
#include <math.h>

#define NUM_BINS 36
#define WARPS_PER_BLOCK 4
#define PATCH 32
#define HSLOT (NUM_BINS * 32)      // 1152 floats: hist[36][32]
#define WSTRIDE 1232               // hist + raw(36->40) + smoothed(36->40)

// Discrete Gaussian smoothing kernel (sigma=1.6, ksize=5), computed analytically:
// k_j = I_|j|(2.56) / (I_0 + 2 I_1 + 2 I_2)   (the e^{-t} factor cancels).
// I_0(2.56)=3.4450257856, I_1=2.6573853906, I_2=1.3689427076, D=11.4976819820.
#define SK0 0.11906250f
#define SK1 0.23112358f
#define SK2 0.29962786f

// ---------------------------------------------------------------------------
// atan2, ~1 ulp: 1 fast-div + 9 FMA minimax poly (SLEEF-style coefficients).
// ---------------------------------------------------------------------------
__device__ __forceinline__ float fast_atan2f(float y, float x) {
    float ax = fabsf(x), ay = fabsf(y);
    float mx = fmaxf(ax, ay);
    float mn = fminf(ax, ay);
    float t = __fdividef(mn, mx);
    float s = t * t;
    float p =            0.00282363896258175373077393f;
    p = fmaf(p, s,      -0.0159569028764963150024414f);
    p = fmaf(p, s,       0.0425049886107444763183594f);
    p = fmaf(p, s,      -0.0748900920152664184570312f);
    p = fmaf(p, s,       0.106347933411598205566406f);
    p = fmaf(p, s,      -0.142027363181114196777344f);
    p = fmaf(p, s,       0.199926957488059997558594f);
    p = fmaf(p, s,      -0.333331018686294555664062f);
    float a = fmaf(p * s, t, t);
    if (ay > ax)  a = 1.5707963267948966f - a;
    if (x < 0.0f) a = 3.1415926535897931f - a;
    return copysignf(a, y);
}

// ---------------------------------------------------------------------------
// Main kernel: one warp per patch, fully warp-autonomous (no __syncthreads).
//  - Gaussian weight factor computed per-warp (expf + shfl reduce)
//  - patch column per lane, rows in registers; Sobel via shfl of column sums
//  - per-lane histogram columns in smem (bank-conflict-free, atomic-free)
//  - warp-level reduce + smooth (all 36 bins, FFMA-imm taps) + argmax + fit
// ---------------------------------------------------------------------------
__global__ void __launch_bounds__(WARPS_PER_BLOCK * 32)
patch_orient_kernel(const float* __restrict__ in, float* __restrict__ out) {
    __shared__ float hist[WARPS_PER_BLOCK * WSTRIDE];

    const unsigned FULL = 0xffffffffu;
    int tid  = threadIdx.x;
    int warp = tid >> 5;
    int lane = tid & 31;
    int patch = blockIdx.x * WARPS_PER_BLOCK + warp;

    // Per-lane Gaussian weight: w[lane] = exp(-x^2/(2*sigma^2)) / sum,
    // sigma = 32/6  ->  1/(2 sigma^2) = 36/2048 = 0.017578125 exactly.
    float xg = (float)lane - 15.5f;
    float g  = expf(-xg * xg * 0.017578125f);
    float gs = g;
#pragma unroll
    for (int off = 16; off; off >>= 1) gs += __shfl_xor_sync(FULL, gs, off);
    const float wfull = g / gs;          // weight of this lane's column/row
    const float wc = wfull;

    const float* src = in + (size_t)patch * (PATCH * PATCH) + lane;
    float p[PATCH];
#pragma unroll
    for (int r = 0; r < PATCH; r++) p[r] = src[r * PATCH];

    float* h = hist + warp * WSTRIDE;
#pragma unroll
    for (int b = 0; b < NUM_BINS; b++) h[b * 32 + lane] = 0.0f;

    const int lm1 = (lane == 0) ? 0 : lane - 1;
    const int lp1 = (lane == 31) ? 31 : lane + 1;

#pragma unroll
    for (int r = 0; r < PATCH; r++) {
        float pm = p[(r == 0) ? 0 : r - 1];
        float pp = p[(r == PATCH - 1) ? PATCH - 1 : r + 1];
        float srow = fmaf(2.0f, p[r], pm + pp);   // 1-2-1 column sum (for gx)
        float d    = pp - pm;                     // row diff (for gy)

        float sl = __shfl_sync(FULL, srow, lm1);
        float sr = __shfl_sync(FULL, srow, lp1);
        float dl = __shfl_sync(FULL, d, lm1);
        float dr = __shfl_sync(FULL, d, lp1);
        float wr = __shfl_sync(FULL, wfull, r);   // row weight (literal lane)

        float gx = (sr - sl) * 0.125f;
        float gy = fmaf(2.0f, d, dl + dr) * 0.125f;

        float m2  = fmaf(gx, gx, fmaf(gy, gy, 1e-8f));
        float mag = m2 * rsqrtf(m2) * (wr * wc);

        float at = fast_atan2f(gy, gx + 1e-8f);
        // o = 36*(at + 3*pi)/(2*pi) = at * (18/pi) + 54,  o in (36, 72]
        float o  = fmaf(at, 5.7295779513082320877f, 54.0f);
        float fo = floorf(o);
        float wo1 = o - fo;
        int i0 = (int)fo - 36;
        if (i0 < 0) i0 += 36;            // guards for o at/near range ends
        if (i0 >= 36) i0 -= 36;
        int i1 = i0 + 1;
        if (i1 == 36) i1 = 0;

        float w1v = wo1 * mag;
        float w0v = mag - w1v;
        h[i0 * 32 + lane] += w0v;        // bank == lane: conflict-free
        h[i1 * 32 + lane] += w1v;
    }
    __syncwarp();

    // Reduce 36 bins x 32 lane-slots. Lane l sums bin l; lanes 0-3 also bins 32-35.
    float acc = 0.0f, acc2 = 0.0f;
#pragma unroll
    for (int k = 0; k < 32; k++) {
        int kk = (k + lane) & 31;                    // rotate -> bank-conflict-free
        acc += h[lane * 32 + kk];
        if (lane < 4) acc2 += h[(32 + lane) * 32 + kk];
    }
    float* red  = h + HSLOT;        // 36 raw bins
    float* red2 = red + 40;         // 36 smoothed bins
    red[lane] = acc;
    if (lane < 4) red[32 + lane] = acc2;
    __syncwarp();

    // Smooth all 36 bins with wrap-padded 5-tap kernel (immediate coefficients).
    float sv = SK0 * red[(lane + 34) % 36];
    sv = fmaf(SK1, red[(lane + 35) % 36], sv);
    sv = fmaf(SK2, red[lane],            sv);
    sv = fmaf(SK1, red[(lane + 1) % 36], sv);
    sv = fmaf(SK0, red[(lane + 2) % 36], sv);
    red2[lane] = sv;
    float sv2 = -1e30f;
    if (lane < 4) {
        int b = 32 + lane;
        sv2 = SK0 * red[(b + 34) % 36];
        sv2 = fmaf(SK1, red[(b + 35) % 36], sv2);
        sv2 = fmaf(SK2, red[b],             sv2);
        sv2 = fmaf(SK1, red[(b + 1) % 36],  sv2);
        sv2 = fmaf(SK0, red[(b + 2) % 36],  sv2);
        red2[b] = sv2;
    }
    __syncwarp();

    // Per-lane candidate: bin `lane`, optionally replaced by bin `32+lane`
    // (strict > keeps lowest-index-wins tie semantics since 32+lane > lane).
    float v = sv;
    int idx = lane;
    if (lane < 4 && sv2 > v) { v = sv2; idx = 32 + lane; }

    // Warp argmax (lowest index on ties, matching jnp.argmax).
#pragma unroll
    for (int off = 16; off; off >>= 1) {
        float v2 = __shfl_xor_sync(FULL, v, off);
        int   i2 = __shfl_xor_sync(FULL, idx, off);
        if (v2 > v || (v2 == v && i2 < idx)) { v = v2; idx = i2; }
    }

    if (lane == 0) {
        float left  = red2[(idx + 35) % 36];
        float right = red2[(idx + 1) % 36];
        float denom = left + right - 2.0f * v;
        float c = 0.5f * (left - right) / denom;
        // angle = pi - (idx + c) * 2*pi/36   (the /HW scale cancels everywhere)
        float angle = 3.14159265358979f - ((float)idx + c) * 0.17453292519943295f;
        out[patch] = angle;
    }
}

// ---------------------------------------------------------------------------
extern "C" void kernel_launch(void* const* d_in, const int* in_sizes, int n_in,
                              void* d_out, int out_size) {
    const float* patch = (const float*)d_in[0];
    float* out = (float*)d_out;
    int n_patches = in_sizes[0] / (PATCH * PATCH);   // 32768

    int blocks = n_patches / WARPS_PER_BLOCK;        // 8192
    patch_orient_kernel<<<blocks, WARPS_PER_BLOCK * 32>>>(patch, out);
}

// round 4
// speedup vs baseline: 9.3881x; 1.1850x over previous
#include <cuda_runtime.h>
#include <math.h>

#define NUM_BINS 36
#define WARPS_PER_BLOCK 4
#define PATCH 32
#define HBINS 38                   // 36 + 2 overflow bins (36->0, 37->1)
#define HSLOT (HBINS * 32)         // 1216 floats: hist[38][32]
#define WSTRIDE 1296               // hist + raw(40) + smoothed(40)

// Discrete Gaussian smoothing kernel (sigma=1.6, ksize=5), analytically:
// k_j = I_|j|(2.56) / (I_0 + 2 I_1 + 2 I_2)   (the e^{-t} factor cancels).
#define SK0 0.11906250f
#define SK1 0.23112358f
#define SK2 0.29962786f

__device__ __forceinline__ float sqrt_approx(float x) {
    float r;
    asm("sqrt.approx.f32 %0, %1;" : "=f"(r) : "f"(x));
    return r;
}

// ---------------------------------------------------------------------------
// atan2, ~1 ulp: 1 fast-div + 9 FMA minimax poly.
// Guarantees result in [-pi, pi] with |result| built as pi - (small>=0).
// ---------------------------------------------------------------------------
__device__ __forceinline__ float fast_atan2f(float y, float x) {
    float ax = fabsf(x), ay = fabsf(y);
    float mx = fmaxf(ax, ay);
    float mn = fminf(ax, ay);
    float t = __fdividef(mn, mx);
    float s = t * t;
    float p =            0.00282363896258175373077393f;
    p = fmaf(p, s,      -0.0159569028764963150024414f);
    p = fmaf(p, s,       0.0425049886107444763183594f);
    p = fmaf(p, s,      -0.0748900920152664184570312f);
    p = fmaf(p, s,       0.106347933411598205566406f);
    p = fmaf(p, s,      -0.142027363181114196777344f);
    p = fmaf(p, s,       0.199926957488059997558594f);
    p = fmaf(p, s,      -0.333331018686294555664062f);
    float a = fmaf(p * s, t, t);
    if (ay > ax)  a = 1.5707963267948966f - a;
    if (x < 0.0f) a = 3.1415926535897931f - a;
    return copysignf(a, y);
}

// ---------------------------------------------------------------------------
// Main kernel: one warp per patch, fully warp-autonomous.
//  - per-warp Gaussian weight factor (expf + shfl reduce), 1/8 Sobel scale folded in
//  - patch column per lane, rows in registers; Sobel via shfl of column sums
//  - 38-bin per-lane histogram columns in smem: no wrap guards in hot loop,
//    i1 = i0+1 accessed via [R+128] immediate; bank == lane: conflict-free
//  - warp-level reduce (folding bins 36,37) + smooth + argmax + parabola fit
// ---------------------------------------------------------------------------
__global__ void __launch_bounds__(WARPS_PER_BLOCK * 32)
patch_orient_kernel(const float* __restrict__ in, float* __restrict__ out) {
    __shared__ float hist[WARPS_PER_BLOCK * WSTRIDE];

    const unsigned FULL = 0xffffffffu;
    int tid  = threadIdx.x;
    int warp = tid >> 5;
    int lane = tid & 31;
    int patch = blockIdx.x * WARPS_PER_BLOCK + warp;

    // Per-lane Gaussian weight: w[lane] = exp(-x^2/(2*sigma^2)) / sum,
    // sigma = 32/6 -> 1/(2 sigma^2) = 36/2048 = 0.017578125 exactly.
    float xg = (float)lane - 15.5f;
    float g  = expf(-xg * xg * 0.017578125f);
    float gs = g;
#pragma unroll
    for (int off = 16; off; off >>= 1) gs += __shfl_xor_sync(FULL, gs, off);
    const float wfull = g / gs;            // row/column weight of this lane
    const float wcs   = wfull * 0.125f;    // column weight with Sobel 1/8 folded in

    const float* src = in + (size_t)patch * (PATCH * PATCH) + lane;
    float p[PATCH];
#pragma unroll
    for (int r = 0; r < PATCH; r++) p[r] = src[r * PATCH];

    float* h = hist + warp * WSTRIDE;
#pragma unroll
    for (int b = 0; b < HBINS; b++) h[b * 32 + lane] = 0.0f;

    // Base pointer pre-biased by -36 rows so addr = base + i0raw*128 (F2I+LEA).
    float* hl = h + lane - 36 * 32;

    const int lm1 = (lane == 0) ? 0 : lane - 1;
    const int lp1 = (lane == 31) ? 31 : lane + 1;

#pragma unroll
    for (int r = 0; r < PATCH; r++) {
        float pm = p[(r == 0) ? 0 : r - 1];
        float pp = p[(r == PATCH - 1) ? PATCH - 1 : r + 1];
        float srow = fmaf(2.0f, p[r], pm + pp);   // 1-2-1 column sum (8*gx source)
        float d    = pp - pm;                     // row diff (8*gy source)

        float sl = __shfl_sync(FULL, srow, lm1);
        float sr = __shfl_sync(FULL, srow, lp1);
        float dl = __shfl_sync(FULL, d, lm1);
        float dr = __shfl_sync(FULL, d, lp1);
        float wr = __shfl_sync(FULL, wfull, r);   // row weight (literal lane)

        float GX = sr - sl;                       // 8*gx
        float GY = fmaf(2.0f, d, dl + dr);        // 8*gy

        // mag*w = sqrt(gx^2+gy^2+1e-8) * w = sqrt(GX^2+GY^2+6.4e-7) * (w/8)
        float M2  = fmaf(GX, GX, fmaf(GY, GY, 6.4e-7f));
        float mag = sqrt_approx(M2) * (wr * wcs);

        float at = fast_atan2f(GY, GX + 8e-8f);
        // o = 36*(at + 3*pi)/(2*pi) = at * (18/pi) + 54,  o in [36, 72]
        float o  = fmaf(at, 5.7295779513082320877f, 54.0f);
        o = fmaxf(o, 36.0f);                      // guard -pi rounding edge
        float fo = floorf(o);
        float wo1 = o - fo;
        int i0raw = (int)fo;                      // in [36, 72]

        float w1v = wo1 * mag;
        float w0v = mag - w1v;
        float* a = hl + i0raw * 32;               // bank == lane: conflict-free
        a[0]  += w0v;                             // bin i0
        a[32] += w1v;                             // bin i0+1, [R+128] immediate
    }
    __syncwarp();

    // Reduce 38 bins x 32 lane-slots. Lane l sums bin l; lanes 0-5 also bins 32+l.
    float acc = 0.0f, acc2 = 0.0f;
#pragma unroll
    for (int k = 0; k < 32; k++) {
        int kk = (k + lane) & 31;                 // rotate -> bank-conflict-free
        acc += h[lane * 32 + kk];
        if (lane < 6) acc2 += h[(32 + lane) * 32 + kk];
    }
    // Fold overflow bins: 36 -> 0, 37 -> 1 (held by lanes 4, 5 in acc2).
    float b36 = __shfl_sync(FULL, acc2, 4);
    float b37 = __shfl_sync(FULL, acc2, 5);
    if (lane == 0) acc += b36;
    if (lane == 1) acc += b37;

    float* red  = h + HSLOT;        // 36 raw bins
    float* red2 = red + 40;         // 36 smoothed bins
    red[lane] = acc;
    if (lane < 4) red[32 + lane] = acc2;
    __syncwarp();

    // Smooth all 36 bins with wrap-padded 5-tap kernel (immediate coefficients).
    float sv = SK0 * red[(lane + 34) % 36];
    sv = fmaf(SK1, red[(lane + 35) % 36], sv);
    sv = fmaf(SK2, red[lane],            sv);
    sv = fmaf(SK1, red[(lane + 1) % 36], sv);
    sv = fmaf(SK0, red[(lane + 2) % 36], sv);
    red2[lane] = sv;
    float sv2 = -1e30f;
    if (lane < 4) {
        int b = 32 + lane;
        sv2 = SK0 * red[(b + 34) % 36];
        sv2 = fmaf(SK1, red[(b + 35) % 36], sv2);
        sv2 = fmaf(SK2, red[b],             sv2);
        sv2 = fmaf(SK1, red[(b + 1) % 36],  sv2);
        sv2 = fmaf(SK0, red[(b + 2) % 36],  sv2);
        red2[b] = sv2;
    }
    __syncwarp();

    // Per-lane candidate: bin `lane`, optionally replaced by bin `32+lane`
    // (strict > keeps lowest-index-wins tie semantics since 32+lane > lane).
    float v = sv;
    int idx = lane;
    if (lane < 4 && sv2 > v) { v = sv2; idx = 32 + lane; }

    // Warp argmax (lowest index on ties, matching jnp.argmax).
#pragma unroll
    for (int off = 16; off; off >>= 1) {
        float v2 = __shfl_xor_sync(FULL, v, off);
        int   i2 = __shfl_xor_sync(FULL, idx, off);
        if (v2 > v || (v2 == v && i2 < idx)) { v = v2; idx = i2; }
    }

    if (lane == 0) {
        float left  = red2[(idx + 35) % 36];
        float right = red2[(idx + 1) % 36];
        float denom = left + right - 2.0f * v;
        float c = 0.5f * (left - right) / denom;
        // angle = pi - (idx + c) * 2*pi/36   (the /HW scale cancels everywhere)
        float angle = 3.14159265358979f - ((float)idx + c) * 0.17453292519943295f;
        out[patch] = angle;
    }
}

// ---------------------------------------------------------------------------
extern "C" void kernel_launch(void* const* d_in, const int* in_sizes, int n_in,
                              void* d_out, int out_size) {
    const float* patch = (const float*)d_in[0];
    float* out = (float*)d_out;
    int n_patches = in_sizes[0] / (PATCH * PATCH);   // 32768

    int blocks = n_patches / WARPS_PER_BLOCK;        // 8192
    patch_orient_kernel<<<blocks, WARPS_PER_BLOCK * 32>>>(patch, out);
}

// round 5
// speedup vs baseline: 10.3850x; 1.1062x over previous
#include <cuda_runtime.h>
#include <math.h>

#define NUM_BINS 36
#define WARPS_PER_BLOCK 4
#define PATCH 32
#define HBINS 38                   // 36 + 2 overflow bins (36->0, 37->1)
#define HSLOT (HBINS * 32)         // 1216 floats: hist[38][32]
#define WSTRIDE 1296               // hist + raw(40) + smoothed(40)

// Discrete Gaussian smoothing kernel (sigma=1.6, ksize=5), analytically:
// k_j = I_|j|(2.56) / (I_0 + 2 I_1 + 2 I_2)   (the e^{-t} factor cancels).
#define SK0 0.11906250f
#define SK1 0.23112358f
#define SK2 0.29962786f

typedef unsigned long long u64;

// Packed f32x2 ops (sm_103a FFMA2/FADD2/FMUL2 — only reachable via PTX).
#define FMA2(d, a, b, c) asm("fma.rn.f32x2 %0, %1, %2, %3;" : "=l"(d) : "l"(a), "l"(b), "l"(c))
#define MUL2(d, a, b)    asm("mul.rn.f32x2 %0, %1, %2;"     : "=l"(d) : "l"(a), "l"(b))
#define ADD2(d, a, b)    asm("add.rn.f32x2 %0, %1, %2;"     : "=l"(d) : "l"(a), "l"(b))
#define UPK2(l0, h0, s)  asm("mov.b64 {%0, %1}, %2;"        : "=f"(l0), "=f"(h0) : "l"(s))

__device__ __forceinline__ u64 pack2(float a, float b) {
    u64 r; asm("mov.b64 %0, {%1, %2};" : "=l"(r) : "f"(a), "f"(b)); return r;
}

__device__ __forceinline__ float sqrt_approx(float x) {
    float r; asm("sqrt.approx.f32 %0, %1;" : "=f"(r) : "f"(x)); return r;
}

// ---------------------------------------------------------------------------
// Main kernel: one warp per patch, fully warp-autonomous.
// Two rows per iteration; all packable FP32 chains run as f32x2.
// ---------------------------------------------------------------------------
__global__ void __launch_bounds__(WARPS_PER_BLOCK * 32, 8)
patch_orient_kernel(const float* __restrict__ in, float* __restrict__ out) {
    __shared__ float hist[WARPS_PER_BLOCK * WSTRIDE];

    const unsigned FULL = 0xffffffffu;
    int tid  = threadIdx.x;
    int warp = tid >> 5;
    int lane = tid & 31;
    int patch = blockIdx.x * WARPS_PER_BLOCK + warp;

    // Per-lane Gaussian weight: w[lane] = exp(-x^2/(2*sigma^2)) / sum,
    // sigma = 32/6 -> 1/(2 sigma^2) = 36/2048 = 0.017578125 exactly.
    float xg = (float)lane - 15.5f;
    float g  = expf(-xg * xg * 0.017578125f);
    float gs = g;
#pragma unroll
    for (int off = 16; off; off >>= 1) gs += __shfl_xor_sync(FULL, gs, off);
    const float wfull = g / gs;            // row/column weight of this lane
    const float wcs   = wfull * 0.125f;    // column weight, Sobel 1/8 folded in

    // Packed constants (held in register pairs; FFMA2 cannot read cbank).
    const u64 CNEG1 = pack2(-1.0f, -1.0f);
    const u64 CEPS8 = pack2(8e-8f, 8e-8f);
    const u64 CEPS2 = pack2(6.4e-7f, 6.4e-7f);
    const u64 CWCS  = pack2(wcs, wcs);
    const u64 CK18  = pack2(5.7295779513082320877f, 5.7295779513082320877f);
    const u64 CK54  = pack2(54.0f, 54.0f);
    const u64 CC7 = pack2( 0.00282363896258175373077393f,  0.00282363896258175373077393f);
    const u64 CC6 = pack2(-0.0159569028764963150024414f,  -0.0159569028764963150024414f);
    const u64 CC5 = pack2( 0.0425049886107444763183594f,   0.0425049886107444763183594f);
    const u64 CC4 = pack2(-0.0748900920152664184570312f,  -0.0748900920152664184570312f);
    const u64 CC3 = pack2( 0.106347933411598205566406f,    0.106347933411598205566406f);
    const u64 CC2 = pack2(-0.142027363181114196777344f,   -0.142027363181114196777344f);
    const u64 CC1 = pack2( 0.199926957488059997558594f,    0.199926957488059997558594f);
    const u64 CC0 = pack2(-0.333331018686294555664062f,   -0.333331018686294555664062f);

    const float* src = in + (size_t)patch * (PATCH * PATCH) + lane;
    float p[PATCH];
#pragma unroll
    for (int r = 0; r < 8; r++) p[r] = src[r * PATCH];   // prefetch prologue

    float* h = hist + warp * WSTRIDE;
#pragma unroll
    for (int b = 0; b < HBINS; b++) h[b * 32 + lane] = 0.0f;

    // Base pointer pre-biased by -36 rows so addr = base + i0raw*128.
    float* hl = h + lane - 36 * 32;

    const int lm1 = (lane == 0) ? 0 : lane - 1;
    const int lp1 = (lane == 31) ? 31 : lane + 1;

#pragma unroll
    for (int i = 0; i < PATCH / 2; i++) {
        const int r0 = 2 * i, r1 = 2 * i + 1;

        float pm0 = p[(r0 == 0) ? 0 : r0 - 1], pp0 = p[r0 + 1];
        float pm1 = p[r0], pp1 = (r1 == PATCH - 1) ? p[PATCH - 1] : p[r1 + 1];
        float srow0 = fmaf(2.0f, p[r0], pm0 + pp0);
        float srow1 = fmaf(2.0f, p[r1], pm1 + pp1);
        float d0 = pp0 - pm0;
        float d1 = pp1 - pm1;

        float sl0 = __shfl_sync(FULL, srow0, lm1);
        float sr0 = __shfl_sync(FULL, srow0, lp1);
        float dl0 = __shfl_sync(FULL, d0, lm1);
        float dr0 = __shfl_sync(FULL, d0, lp1);
        float sl1 = __shfl_sync(FULL, srow1, lm1);
        float sr1 = __shfl_sync(FULL, srow1, lp1);
        float dl1 = __shfl_sync(FULL, d1, lm1);
        float dr1 = __shfl_sync(FULL, d1, lp1);
        float wr0 = __shfl_sync(FULL, wfull, r0);
        float wr1 = __shfl_sync(FULL, wfull, r1);

        // Prefetch ring: rows r0+8, r0+9 (guards are compile-time).
        if (r0 + 8 < PATCH) p[r0 + 8] = src[(r0 + 8) * PATCH];
        if (r0 + 9 < PATCH) p[r0 + 9] = src[(r0 + 9) * PATCH];

        u64 SL = pack2(sl0, sl1), SR = pack2(sr0, sr1);
        u64 DL = pack2(dl0, dl1), DR = pack2(dr0, dr1);
        u64 DD = pack2(d0, d1);

        u64 GX;  FMA2(GX, SL, CNEG1, SR);        // 8*gx = sr - sl
        u64 GXE; ADD2(GXE, GX, CEPS8);           // + 8e-8 (ref eps, scaled)
        u64 T1;  ADD2(T1, DL, DR);
        u64 T2;  ADD2(T2, DD, DD);
        u64 GY;  ADD2(GY, T1, T2);               // 8*gy = dl + dr + 2d
        u64 M2;  FMA2(M2, GY, GY, CEPS2);
        FMA2(M2, GXE, GXE, M2);

        float m20, m21; UPK2(m20, m21, M2);
        float q0 = sqrt_approx(m20);
        float q1 = sqrt_approx(m21);
        u64 WR = pack2(wr0, wr1);
        u64 WW;  MUL2(WW, WR, CWCS);
        u64 SQ = pack2(q0, q1);
        u64 MAG; MUL2(MAG, SQ, WW);
        float mag0, mag1; UPK2(mag0, mag1, MAG);

        float gx0, gx1, gy0, gy1;
        UPK2(gx0, gx1, GXE);
        UPK2(gy0, gy1, GY);

        // atan2 front (scalar: MUFU + min/max).
        float mx0 = fmaxf(fabsf(gx0), fabsf(gy0));
        float mn0 = fminf(fabsf(gx0), fabsf(gy0));
        float t0  = __fdividef(mn0, mx0);
        float mx1 = fmaxf(fabsf(gx1), fabsf(gy1));
        float mn1 = fminf(fabsf(gx1), fabsf(gy1));
        float t1  = __fdividef(mn1, mx1);

        // Packed 8-term minimax atan poly (~1 ulp).
        u64 T = pack2(t0, t1);
        u64 S;  MUL2(S, T, T);
        u64 P;  FMA2(P, CC7, S, CC6);
        FMA2(P, P, S, CC5);
        FMA2(P, P, S, CC4);
        FMA2(P, P, S, CC3);
        FMA2(P, P, S, CC2);
        FMA2(P, P, S, CC1);
        FMA2(P, P, S, CC0);
        u64 PS; MUL2(PS, P, S);
        u64 A;  FMA2(A, PS, T, T);
        float a0, a1; UPK2(a0, a1, A);

        // Octant fixups (scalar, predicated).
        if (fabsf(gy0) > fabsf(gx0)) a0 = 1.5707963267948966f - a0;
        if (gx0 < 0.0f)              a0 = 3.1415926535897931f - a0;
        float at0 = copysignf(a0, gy0);
        if (fabsf(gy1) > fabsf(gx1)) a1 = 1.5707963267948966f - a1;
        if (gx1 < 0.0f)              a1 = 3.1415926535897931f - a1;
        float at1 = copysignf(a1, gy1);

        // o = at*(18/pi) + 54  in [36, 72]
        u64 AT = pack2(at0, at1);
        u64 O;  FMA2(O, AT, CK18, CK54);
        float o0, o1; UPK2(o0, o1, O);

        // Per-half tail (scalar): fmax is also the NaN guard (FMNMX drops NaN).
        o0 = fmaxf(o0, 36.0f);
        float fo0 = floorf(o0);
        float wo10 = o0 - fo0;
        int i00 = (int)fo0;                     // in [36, 72]
        float w1v0 = wo10 * mag0;
        float w0v0 = mag0 - w1v0;
        float* q0p = hl + i00 * 32;             // bank == lane: conflict-free
        q0p[0]  += w0v0;
        q0p[32] += w1v0;

        o1 = fmaxf(o1, 36.0f);
        float fo1 = floorf(o1);
        float wo11 = o1 - fo1;
        int i01 = (int)fo1;
        float w1v1 = wo11 * mag1;
        float w0v1 = mag1 - w1v1;
        float* q1p = hl + i01 * 32;
        q1p[0]  += w0v1;
        q1p[32] += w1v1;
    }
    __syncwarp();

    // Reduce 38 bins x 32 lane-slots. Lane l sums bin l; lanes 0-5 also bins 32+l.
    float acc = 0.0f, acc2 = 0.0f;
#pragma unroll
    for (int k = 0; k < 32; k++) {
        int kk = (k + lane) & 31;                 // rotate -> bank-conflict-free
        acc += h[lane * 32 + kk];
        if (lane < 6) acc2 += h[(32 + lane) * 32 + kk];
    }
    // Fold overflow bins: 36 -> 0, 37 -> 1 (held by lanes 4, 5 in acc2).
    float b36 = __shfl_sync(FULL, acc2, 4);
    float b37 = __shfl_sync(FULL, acc2, 5);
    if (lane == 0) acc += b36;
    if (lane == 1) acc += b37;

    float* red  = h + HSLOT;        // 36 raw bins
    float* red2 = red + 40;         // 36 smoothed bins
    red[lane] = acc;
    if (lane < 4) red[32 + lane] = acc2;
    __syncwarp();

    // Smooth all 36 bins with wrap-padded 5-tap kernel (immediate coefficients).
    float sv = SK0 * red[(lane + 34) % 36];
    sv = fmaf(SK1, red[(lane + 35) % 36], sv);
    sv = fmaf(SK2, red[lane],            sv);
    sv = fmaf(SK1, red[(lane + 1) % 36], sv);
    sv = fmaf(SK0, red[(lane + 2) % 36], sv);
    red2[lane] = sv;
    float sv2 = -1e30f;
    if (lane < 4) {
        int b = 32 + lane;
        sv2 = SK0 * red[(b + 34) % 36];
        sv2 = fmaf(SK1, red[(b + 35) % 36], sv2);
        sv2 = fmaf(SK2, red[b],             sv2);
        sv2 = fmaf(SK1, red[(b + 1) % 36],  sv2);
        sv2 = fmaf(SK0, red[(b + 2) % 36],  sv2);
        red2[b] = sv2;
    }
    __syncwarp();

    // Per-lane candidate: bin `lane`, optionally replaced by bin `32+lane`
    // (strict > keeps lowest-index-wins tie semantics since 32+lane > lane).
    float v = sv;
    int idx = lane;
    if (lane < 4 && sv2 > v) { v = sv2; idx = 32 + lane; }

    // Warp argmax (lowest index on ties, matching jnp.argmax).
#pragma unroll
    for (int off = 16; off; off >>= 1) {
        float v2 = __shfl_xor_sync(FULL, v, off);
        int   i2 = __shfl_xor_sync(FULL, idx, off);
        if (v2 > v || (v2 == v && i2 < idx)) { v = v2; idx = i2; }
    }

    if (lane == 0) {
        float left  = red2[(idx + 35) % 36];
        float right = red2[(idx + 1) % 36];
        float denom = left + right - 2.0f * v;
        float c = 0.5f * (left - right) / denom;
        // angle = pi - (idx + c) * 2*pi/36   (the /HW scale cancels everywhere)
        float angle = 3.14159265358979f - ((float)idx + c) * 0.17453292519943295f;
        out[patch] = angle;
    }
}

// ---------------------------------------------------------------------------
extern "C" void kernel_launch(void* const* d_in, const int* in_sizes, int n_in,
                              void* d_out, int out_size) {
    const float* patch = (const float*)d_in[0];
    float* out = (float*)d_out;
    int n_patches = in_sizes[0] / (PATCH * PATCH);   // 32768

    int blocks = n_patches / WARPS_PER_BLOCK;        // 8192
    patch_orient_kernel<<<blocks, WARPS_PER_BLOCK * 32>>>(patch, out);
}

// round 6
// speedup vs baseline: 10.4893x; 1.0100x over previous
#include <cuda_runtime.h>
#include <math.h>

#define NUM_BINS 36
#define WARPS_PER_BLOCK 4
#define PATCH 32
#define HBINS 38                   // 36 + 2 overflow bins (36->0, 37->1)
#define HSLOT (HBINS * 32)         // 1216 floats: hist[38][32]
#define WSTRIDE 1296               // hist + raw(40) + smoothed(40)

// Discrete Gaussian smoothing kernel (sigma=1.6, ksize=5), analytically:
// k_j = I_|j|(2.56) / (I_0 + 2 I_1 + 2 I_2)   (the e^{-t} factor cancels).
#define SK0 0.11906250f
#define SK1 0.23112358f
#define SK2 0.29962786f

typedef unsigned long long u64;

// Packed f32x2 ops (sm_103a FFMA2/FADD2/FMUL2 — only reachable via PTX).
#define FMA2(d, a, b, c) asm("fma.rn.f32x2 %0, %1, %2, %3;" : "=l"(d) : "l"(a), "l"(b), "l"(c))
#define MUL2(d, a, b)    asm("mul.rn.f32x2 %0, %1, %2;"     : "=l"(d) : "l"(a), "l"(b))
#define ADD2(d, a, b)    asm("add.rn.f32x2 %0, %1, %2;"     : "=l"(d) : "l"(a), "l"(b))
#define UPK2(l0, h0, s)  asm("mov.b64 {%0, %1}, %2;"        : "=f"(l0), "=f"(h0) : "l"(s))

__device__ __forceinline__ u64 pack2(float a, float b) {
    u64 r; asm("mov.b64 %0, {%1, %2};" : "=l"(r) : "f"(a), "f"(b)); return r;
}

__device__ __forceinline__ float sqrt_approx(float x) {
    float r; asm("sqrt.approx.f32 %0, %1;" : "=f"(r) : "f"(x)); return r;
}

// ---------------------------------------------------------------------------
// Main kernel: one warp per patch, fully warp-autonomous.
// Two rows per iteration; all packable FP32 chains run as f32x2; neighbor
// exchange via 64-bit shuffles of pre-packed (row0,row1) quantities.
// ---------------------------------------------------------------------------
__global__ void __launch_bounds__(WARPS_PER_BLOCK * 32, 8)
patch_orient_kernel(const float* __restrict__ in, float* __restrict__ out) {
    __shared__ __align__(16) float hist[WARPS_PER_BLOCK * WSTRIDE];

    const unsigned FULL = 0xffffffffu;
    int tid  = threadIdx.x;
    int warp = tid >> 5;
    int lane = tid & 31;
    int patch = blockIdx.x * WARPS_PER_BLOCK + warp;

    // Per-lane Gaussian weight: w[lane] = exp(-x^2/(2*sigma^2)) / sum,
    // sigma = 32/6 -> 1/(2 sigma^2) = 36/2048 = 0.017578125 exactly.
    float xg = (float)lane - 15.5f;
    float g  = expf(-xg * xg * 0.017578125f);
    float gs = g;
#pragma unroll
    for (int off = 16; off; off >>= 1) gs += __shfl_xor_sync(FULL, gs, off);
    const float wfull = g / gs;            // row/column weight of this lane
    const float wcs   = wfull * 0.125f;    // column weight, Sobel 1/8 folded in

    // Row-weight pair: lane i holds (w[2i], w[2i+1]) (source lanes 0-15 used).
    float wa = __shfl_sync(FULL, wfull, (lane << 1) & 31);
    float wb = __shfl_sync(FULL, wfull, ((lane << 1) + 1) & 31);
    const u64 WP = pack2(wa, wb);

    // Packed constants (held in register pairs; FFMA2 cannot read cbank).
    const u64 CNEG1 = pack2(-1.0f, -1.0f);
    const u64 CEPS8 = pack2(8e-8f, 8e-8f);
    const u64 CEPS2 = pack2(6.4e-7f, 6.4e-7f);
    const u64 CWCS  = pack2(wcs, wcs);
    const u64 CK18  = pack2(5.7295779513082320877f, 5.7295779513082320877f);
    const u64 CK54  = pack2(54.0f, 54.0f);
    const u64 CC7 = pack2( 0.00282363896258175373077393f,  0.00282363896258175373077393f);
    const u64 CC6 = pack2(-0.0159569028764963150024414f,  -0.0159569028764963150024414f);
    const u64 CC5 = pack2( 0.0425049886107444763183594f,   0.0425049886107444763183594f);
    const u64 CC4 = pack2(-0.0748900920152664184570312f,  -0.0748900920152664184570312f);
    const u64 CC3 = pack2( 0.106347933411598205566406f,    0.106347933411598205566406f);
    const u64 CC2 = pack2(-0.142027363181114196777344f,   -0.142027363181114196777344f);
    const u64 CC1 = pack2( 0.199926957488059997558594f,    0.199926957488059997558594f);
    const u64 CC0 = pack2(-0.333331018686294555664062f,   -0.333331018686294555664062f);

    const float* src = in + (size_t)patch * (PATCH * PATCH) + lane;
    float p[PATCH];
#pragma unroll
    for (int r = 0; r < 8; r++) p[r] = src[r * PATCH];   // prefetch prologue

    float* h = hist + warp * WSTRIDE;
#pragma unroll
    for (int b = 0; b < HBINS / 2; b++)                   // packed zero-init
        *(u64*)(h + b * 64 + lane * 2) = 0ull;

    // Base pointer pre-biased by -36 rows so addr = base + i0raw*128.
    float* hl = h + lane - 36 * 32;

    const int lm1 = (lane == 0) ? 0 : lane - 1;
    const int lp1 = (lane == 31) ? 31 : lane + 1;

#pragma unroll
    for (int i = 0; i < PATCH / 2; i++) {
        const int r0 = 2 * i, r1 = 2 * i + 1;

        // Packed vertical combos. Note pm1 = p[r0], pp0 = p[r1] (overlap).
        float pm0 = p[(r0 == 0) ? 0 : r0 - 1];
        float pp1 = (r1 == PATCH - 1) ? p[PATCH - 1] : p[r1 + 1];
        u64 PM = pack2(pm0, p[r0]);
        u64 PC = pack2(p[r0], p[r1]);
        u64 PP = pack2(p[r1], pp1);

        u64 SUMV; ADD2(SUMV, PM, PP);
        u64 PC2;  ADD2(PC2, PC, PC);
        u64 SROW; ADD2(SROW, PC2, SUMV);         // 1-2-1 column sum (8*gx src)
        u64 DD;   FMA2(DD, PM, CNEG1, PP);       // vertical diff (8*gy src)

        // 64-bit neighbor shuffles (results stay packed).
        u64 SL = __shfl_sync(FULL, SROW, lm1);
        u64 SR = __shfl_sync(FULL, SROW, lp1);
        u64 DL = __shfl_sync(FULL, DD, lm1);
        u64 DR = __shfl_sync(FULL, DD, lp1);
        u64 WRP = __shfl_sync(FULL, WP, i);      // (w[r0], w[r1])

        // Prefetch ring: rows r0+8, r0+9 (guards are compile-time).
        if (r0 + 8 < PATCH) p[r0 + 8] = src[(r0 + 8) * PATCH];
        if (r0 + 9 < PATCH) p[r0 + 9] = src[(r0 + 9) * PATCH];

        u64 GX;  FMA2(GX, SL, CNEG1, SR);        // 8*gx = sr - sl
        u64 GXE; ADD2(GXE, GX, CEPS8);           // + 8e-8 (ref eps, scaled)
        u64 T1;  ADD2(T1, DL, DR);
        u64 T2;  ADD2(T2, DD, DD);
        u64 GY;  ADD2(GY, T1, T2);               // 8*gy = dl + dr + 2d
        u64 M2;  FMA2(M2, GY, GY, CEPS2);
        FMA2(M2, GXE, GXE, M2);

        float m20, m21; UPK2(m20, m21, M2);
        float q0 = sqrt_approx(m20);
        float q1 = sqrt_approx(m21);
        u64 WW;  MUL2(WW, WRP, CWCS);
        u64 SQ = pack2(q0, q1);
        u64 MAG; MUL2(MAG, SQ, WW);
        float mag0, mag1; UPK2(mag0, mag1, MAG);

        float gx0, gx1, gy0, gy1;
        UPK2(gx0, gx1, GXE);
        UPK2(gy0, gy1, GY);

        // atan2 front (scalar: MUFU + min/max with |.| operand modifiers).
        float mx0 = fmaxf(fabsf(gx0), fabsf(gy0));
        float mn0 = fminf(fabsf(gx0), fabsf(gy0));
        float t0  = __fdividef(mn0, mx0);
        float mx1 = fmaxf(fabsf(gx1), fabsf(gy1));
        float mn1 = fminf(fabsf(gx1), fabsf(gy1));
        float t1  = __fdividef(mn1, mx1);

        // Packed 8-term minimax atan poly (~1 ulp).
        u64 T = pack2(t0, t1);
        u64 S;  MUL2(S, T, T);
        u64 P;  FMA2(P, CC7, S, CC6);
        FMA2(P, P, S, CC5);
        FMA2(P, P, S, CC4);
        FMA2(P, P, S, CC3);
        FMA2(P, P, S, CC2);
        FMA2(P, P, S, CC1);
        FMA2(P, P, S, CC0);
        u64 PS; MUL2(PS, P, S);
        u64 A;  FMA2(A, PS, T, T);
        float a0, a1; UPK2(a0, a1, A);

        // Octant fixups (scalar, predicated).
        if (fabsf(gy0) > fabsf(gx0)) a0 = 1.5707963267948966f - a0;
        if (gx0 < 0.0f)              a0 = 3.1415926535897931f - a0;
        float at0 = copysignf(a0, gy0);
        if (fabsf(gy1) > fabsf(gx1)) a1 = 1.5707963267948966f - a1;
        if (gx1 < 0.0f)              a1 = 3.1415926535897931f - a1;
        float at1 = copysignf(a1, gy1);

        // o = at*(18/pi) + 54  in [36, 72]
        u64 AT = pack2(at0, at1);
        u64 O;  FMA2(O, AT, CK18, CK54);
        float o0, o1; UPK2(o0, o1, O);

        // Per-half tail (scalar): fmax is also the NaN guard (FMNMX drops NaN).
        o0 = fmaxf(o0, 36.0f);
        float fo0 = floorf(o0);
        float wo10 = o0 - fo0;
        int i00 = (int)fo0;                     // in [36, 72]
        float w1v0 = wo10 * mag0;
        float w0v0 = mag0 - w1v0;
        float* q0p = hl + i00 * 32;             // bank == lane: conflict-free
        q0p[0]  += w0v0;
        q0p[32] += w1v0;

        o1 = fmaxf(o1, 36.0f);
        float fo1 = floorf(o1);
        float wo11 = o1 - fo1;
        int i01 = (int)fo1;
        float w1v1 = wo11 * mag1;
        float w0v1 = mag1 - w1v1;
        float* q1p = hl + i01 * 32;
        q1p[0]  += w0v1;
        q1p[32] += w1v1;
    }
    __syncwarp();

    // Packed reduce: 38 bins x 32 lane-slots as 16 u64 per bin, lane-rotated.
    // Lane l sums bin l; lanes 0-5 also bins 32+l.
    u64 ACC = 0ull;
#pragma unroll
    for (int k = 0; k < 16; k++) {
        int kk = ((k + lane) & 15) * 2;          // rotate -> spread banks
        u64 v = *(const u64*)(h + lane * 32 + kk);
        ADD2(ACC, ACC, v);
    }
    float aLo, aHi; UPK2(aLo, aHi, ACC);
    float acc = aLo + aHi;

    float acc2 = 0.0f;
    if (lane < 6) {
        u64 ACC2 = 0ull;
#pragma unroll
        for (int k = 0; k < 16; k++) {
            int kk = ((k + lane) & 15) * 2;
            u64 v = *(const u64*)(h + (32 + lane) * 32 + kk);
            ADD2(ACC2, ACC2, v);
        }
        float bLo, bHi; UPK2(bLo, bHi, ACC2);
        acc2 = bLo + bHi;
    }
    // Fold overflow bins: 36 -> 0, 37 -> 1 (held by lanes 4, 5 in acc2).
    float b36 = __shfl_sync(FULL, acc2, 4);
    float b37 = __shfl_sync(FULL, acc2, 5);
    if (lane == 0) acc += b36;
    if (lane == 1) acc += b37;

    float* red  = h + HSLOT;        // 36 raw bins
    float* red2 = red + 40;         // 36 smoothed bins
    red[lane] = acc;
    if (lane < 4) red[32 + lane] = acc2;
    __syncwarp();

    // Smooth all 36 bins with wrap-padded 5-tap kernel (immediate coefficients).
    float sv = SK0 * red[(lane + 34) % 36];
    sv = fmaf(SK1, red[(lane + 35) % 36], sv);
    sv = fmaf(SK2, red[lane],            sv);
    sv = fmaf(SK1, red[(lane + 1) % 36], sv);
    sv = fmaf(SK0, red[(lane + 2) % 36], sv);
    red2[lane] = sv;
    float sv2 = -1e30f;
    if (lane < 4) {
        int b = 32 + lane;
        sv2 = SK0 * red[(b + 34) % 36];
        sv2 = fmaf(SK1, red[(b + 35) % 36], sv2);
        sv2 = fmaf(SK2, red[b],             sv2);
        sv2 = fmaf(SK1, red[(b + 1) % 36],  sv2);
        sv2 = fmaf(SK0, red[(b + 2) % 36],  sv2);
        red2[b] = sv2;
    }
    __syncwarp();

    // Per-lane candidate: bin `lane`, optionally replaced by bin `32+lane`
    // (strict > keeps lowest-index-wins tie semantics since 32+lane > lane).
    float v = sv;
    int idx = lane;
    if (lane < 4 && sv2 > v) { v = sv2; idx = 32 + lane; }

    // Warp argmax (lowest index on ties, matching jnp.argmax).
#pragma unroll
    for (int off = 16; off; off >>= 1) {
        float v2 = __shfl_xor_sync(FULL, v, off);
        int   i2 = __shfl_xor_sync(FULL, idx, off);
        if (v2 > v || (v2 == v && i2 < idx)) { v = v2; idx = i2; }
    }

    if (lane == 0) {
        float left  = red2[(idx + 35) % 36];
        float right = red2[(idx + 1) % 36];
        float denom = left + right - 2.0f * v;
        float c = 0.5f * (left - right) / denom;
        // angle = pi - (idx + c) * 2*pi/36   (the /HW scale cancels everywhere)
        float angle = 3.14159265358979f - ((float)idx + c) * 0.17453292519943295f;
        out[patch] = angle;
    }
}

// ---------------------------------------------------------------------------
extern "C" void kernel_launch(void* const* d_in, const int* in_sizes, int n_in,
                              void* d_out, int out_size) {
    const float* patch = (const float*)d_in[0];
    float* out = (float*)d_out;
    int n_patches = in_sizes[0] / (PATCH * PATCH);   // 32768

    int blocks = n_patches / WARPS_PER_BLOCK;        // 8192
    patch_orient_kernel<<<blocks, WARPS_PER_BLOCK * 32>>>(patch, out);
}

// round 7
// speedup vs baseline: 10.6251x; 1.0129x over previous
#include <cuda_runtime.h>
#include <math.h>

#define NUM_BINS 36
#define WARPS_PER_BLOCK 4
#define PATCH 32
#define HBINS 38                   // 36 + 2 overflow bins (36->0, 37->1)
#define HSLOT (HBINS * 32)         // 1216 floats: hist[38][32]
#define WTAB  1296                 // u64 row-weight-pair table (16 entries)
#define WSTRIDE 1328               // hist + raw(40) + smoothed(40) + wtab(32)

// Discrete Gaussian smoothing kernel (sigma=1.6, ksize=5), analytically:
// k_j = I_|j|(2.56) / (I_0 + 2 I_1 + 2 I_2)   (the e^{-t} factor cancels).
#define SK0 0.11906250f
#define SK1 0.23112358f
#define SK2 0.29962786f

typedef unsigned long long u64;

// Packed f32x2 ops (sm_103a FFMA2/FADD2/FMUL2 — only reachable via PTX).
#define FMA2(d, a, b, c) asm("fma.rn.f32x2 %0, %1, %2, %3;" : "=l"(d) : "l"(a), "l"(b), "l"(c))
#define MUL2(d, a, b)    asm("mul.rn.f32x2 %0, %1, %2;"     : "=l"(d) : "l"(a), "l"(b))
#define ADD2(d, a, b)    asm("add.rn.f32x2 %0, %1, %2;"     : "=l"(d) : "l"(a), "l"(b))
#define UPK2(l0, h0, s)  asm("mov.b64 {%0, %1}, %2;"        : "=f"(l0), "=f"(h0) : "l"(s))

__device__ __forceinline__ u64 pack2(float a, float b) {
    u64 r; asm("mov.b64 %0, {%1, %2};" : "=l"(r) : "f"(a), "f"(b)); return r;
}

__device__ __forceinline__ float sqrt_approx(float x) {
    float r; asm("sqrt.approx.f32 %0, %1;" : "=f"(r) : "f"(x)); return r;
}

// ---------------------------------------------------------------------------
// Main kernel: one warp per patch, fully warp-autonomous.
// Two rows per iteration; all packable FP32 chains run as f32x2.
// atan poly is pre-scaled by 18/pi so the bin index falls out directly.
// ---------------------------------------------------------------------------
__global__ void __launch_bounds__(WARPS_PER_BLOCK * 32, 9)
patch_orient_kernel(const float* __restrict__ in, float* __restrict__ out) {
    __shared__ __align__(16) float hist[WARPS_PER_BLOCK * WSTRIDE];

    const unsigned FULL = 0xffffffffu;
    int tid  = threadIdx.x;
    int warp = tid >> 5;
    int lane = tid & 31;
    int patch = blockIdx.x * WARPS_PER_BLOCK + warp;

    // Per-lane Gaussian weight: w[lane] = exp(-x^2/(2*sigma^2)) / sum,
    // sigma = 32/6 -> 1/(2 sigma^2) = 36/2048 = 0.017578125 exactly.
    float xg = (float)lane - 15.5f;
    float g  = expf(-xg * xg * 0.017578125f);
    float gs = g;
#pragma unroll
    for (int off = 16; off; off >>= 1) gs += __shfl_xor_sync(FULL, gs, off);
    const float wfull = g / gs;            // row/column weight of this lane
    const float wcs   = wfull * 0.125f;    // column weight, Sobel 1/8 folded in

    float* h = hist + warp * WSTRIDE;
    u64*   wt = (u64*)(h + WTAB);          // 16 row-weight pairs

    // Build row-weight pair table: wt[i] = (w[2i], w[2i+1]).
    float wa = __shfl_sync(FULL, wfull, (lane << 1) & 31);
    float wb = __shfl_sync(FULL, wfull, ((lane << 1) + 1) & 31);
    if (lane < 16) wt[lane] = pack2(wa, wb);

#pragma unroll
    for (int b = 0; b < HBINS / 2; b++)                   // packed zero-init
        *(u64*)(h + b * 64 + lane * 2) = 0ull;
    __syncwarp();   // init/table writes cross lane columns -> publish first

    // Packed constants (register pairs; FFMA2 cannot read cbank).
    // Poly coefficients are the ~1ulp atan minimax set PRE-SCALED by 18/pi.
    const u64 CNEG1 = pack2(-1.0f, -1.0f);
    const u64 CEPS8 = pack2(8e-8f, 8e-8f);
    const u64 CEPS2 = pack2(6.4e-7f, 6.4e-7f);
    const u64 CWCS  = pack2(wcs, wcs);
    const u64 CK    = pack2(5.7295779513082321f, 5.7295779513082321f); // 18/pi
    const u64 CC7 = pack2( 0.0161782457f,  0.0161782457f);
    const u64 CC6 = pack2(-0.0914263090f, -0.0914263090f);
    const u64 CC5 = pack2( 0.2435356455f,  0.2435356455f);
    const u64 CC4 = pack2(-0.4290686200f, -0.4290686200f);
    const u64 CC3 = pack2( 0.6093287740f,  0.6093287740f);
    const u64 CC2 = pack2(-0.8137568480f, -0.8137568480f);
    const u64 CC1 = pack2( 1.1454970880f,  1.1454970880f);
    const u64 CC0 = pack2(-1.9098460550f, -1.9098460550f);

    const float* src = in + (size_t)patch * (PATCH * PATCH) + lane;
    float p[PATCH];
#pragma unroll
    for (int r = 0; r < 8; r++) p[r] = src[r * PATCH];   // prefetch prologue

    // Base pointer pre-biased by -36 rows so addr = base + i0raw*128.
    float* hl = h + lane - 36 * 32;

    const int lm1 = (lane == 0) ? 0 : lane - 1;
    const int lp1 = (lane == 31) ? 31 : lane + 1;

#pragma unroll
    for (int i = 0; i < PATCH / 2; i++) {
        const int r0 = 2 * i, r1 = 2 * i + 1;

        // Packed vertical combos. Note pm1 = p[r0], pp0 = p[r1] (overlap).
        float pm0 = p[(r0 == 0) ? 0 : r0 - 1];
        float pp1 = (r1 == PATCH - 1) ? p[PATCH - 1] : p[r1 + 1];
        u64 PM = pack2(pm0, p[r0]);
        u64 PC = pack2(p[r0], p[r1]);
        u64 PP = pack2(p[r1], pp1);

        u64 SUMV; ADD2(SUMV, PM, PP);
        u64 PC2;  ADD2(PC2, PC, PC);
        u64 SROW; ADD2(SROW, PC2, SUMV);         // 1-2-1 column sum (8*gx src)
        u64 DD;   FMA2(DD, PM, CNEG1, PP);       // vertical diff (8*gy src)

        // 64-bit neighbor shuffles (results stay packed).
        u64 SL = __shfl_sync(FULL, SROW, lm1);
        u64 SR = __shfl_sync(FULL, SROW, lp1);
        u64 DL = __shfl_sync(FULL, DD, lm1);
        u64 DR = __shfl_sync(FULL, DD, lp1);
        u64 WRP = wt[i];                         // (w[r0], w[r1]) broadcast LDS

        // Prefetch ring: rows r0+8, r0+9 (guards are compile-time).
        if (r0 + 8 < PATCH) p[r0 + 8] = src[(r0 + 8) * PATCH];
        if (r0 + 9 < PATCH) p[r0 + 9] = src[(r0 + 9) * PATCH];

        u64 GX;  FMA2(GX, SL, CNEG1, SR);        // 8*gx = sr - sl
        u64 GXE; ADD2(GXE, GX, CEPS8);           // + 8e-8 (ref eps, scaled)
        u64 T1;  ADD2(T1, DL, DR);
        u64 T2;  ADD2(T2, DD, DD);
        u64 GY;  ADD2(GY, T1, T2);               // 8*gy = dl + dr + 2d
        u64 M2;  FMA2(M2, GY, GY, CEPS2);
        FMA2(M2, GXE, GXE, M2);

        float m20, m21; UPK2(m20, m21, M2);
        float q0 = sqrt_approx(m20);
        float q1 = sqrt_approx(m21);
        u64 WW;  MUL2(WW, WRP, CWCS);
        u64 SQ = pack2(q0, q1);
        u64 MAG; MUL2(MAG, SQ, WW);
        float mag0, mag1; UPK2(mag0, mag1, MAG);

        float gx0, gx1, gy0, gy1;
        UPK2(gx0, gx1, GXE);
        UPK2(gy0, gy1, GY);

        // atan2 front (scalar: MUFU + min/max with |.| operand modifiers).
        float mx0 = fmaxf(fabsf(gx0), fabsf(gy0));
        float mn0 = fminf(fabsf(gx0), fabsf(gy0));
        float t0  = __fdividef(mn0, mx0);
        float mx1 = fmaxf(fabsf(gx1), fabsf(gy1));
        float mn1 = fminf(fabsf(gx1), fabsf(gy1));
        float t1  = __fdividef(mn1, mx1);

        // Packed pre-scaled atan poly: u = (18/pi)*atan(t), u in [0, 4.5].
        u64 T = pack2(t0, t1);
        u64 S;  MUL2(S, T, T);
        u64 P;  FMA2(P, CC7, S, CC6);
        FMA2(P, P, S, CC5);
        FMA2(P, P, S, CC4);
        FMA2(P, P, S, CC3);
        FMA2(P, P, S, CC2);
        FMA2(P, P, S, CC1);
        FMA2(P, P, S, CC0);
        FMA2(P, P, S, CK);                       // Q = 18/pi + s*P(s)
        u64 U;  MUL2(U, P, T);                   // u = Q*t
        float u0, u1; UPK2(u0, u1, U);

        // Octant fixups in bin units (pi/2 -> 9, pi -> 18).
        if (fabsf(gy0) > fabsf(gx0)) u0 = 9.0f  - u0;
        if (gx0 < 0.0f)              u0 = 18.0f - u0;
        float v0 = copysignf(u0, gy0);
        if (fabsf(gy1) > fabsf(gx1)) u1 = 9.0f  - u1;
        if (gx1 < 0.0f)              u1 = 18.0f - u1;
        float v1 = copysignf(u1, gy1);

        // Per-half tail: o = v + 54 in [36, 72]; fmax is also the NaN guard.
        float o0 = fmaxf(v0 + 54.0f, 36.0f);
        float fo0 = floorf(o0);
        float wo10 = o0 - fo0;
        int i00 = (int)fo0;                     // in [36, 72]
        float w1v0 = wo10 * mag0;
        float w0v0 = mag0 - w1v0;
        float* q0p = hl + i00 * 32;             // bank == lane: conflict-free
        q0p[0]  += w0v0;
        q0p[32] += w1v0;

        float o1 = fmaxf(v1 + 54.0f, 36.0f);
        float fo1 = floorf(o1);
        float wo11 = o1 - fo1;
        int i01 = (int)fo1;
        float w1v1 = wo11 * mag1;
        float w0v1 = mag1 - w1v1;
        float* q1p = hl + i01 * 32;
        q1p[0]  += w0v1;
        q1p[32] += w1v1;
    }
    __syncwarp();

    // Packed reduce: 38 bins x 32 lane-slots as 16 u64 per bin, lane-rotated.
    // Lane l sums bin l; lanes 0-5 also bins 32+l.
    u64 ACC = 0ull;
#pragma unroll
    for (int k = 0; k < 16; k++) {
        int kk = ((k + lane) & 15) * 2;          // rotate -> spread banks
        u64 v = *(const u64*)(h + lane * 32 + kk);
        ADD2(ACC, ACC, v);
    }
    float aLo, aHi; UPK2(aLo, aHi, ACC);
    float acc = aLo + aHi;

    float acc2 = 0.0f;
    if (lane < 6) {
        u64 ACC2 = 0ull;
#pragma unroll
        for (int k = 0; k < 16; k++) {
            int kk = ((k + lane) & 15) * 2;
            u64 v = *(const u64*)(h + (32 + lane) * 32 + kk);
            ADD2(ACC2, ACC2, v);
        }
        float bLo, bHi; UPK2(bLo, bHi, ACC2);
        acc2 = bLo + bHi;
    }
    // Fold overflow bins: 36 -> 0, 37 -> 1 (held by lanes 4, 5 in acc2).
    float b36 = __shfl_sync(FULL, acc2, 4);
    float b37 = __shfl_sync(FULL, acc2, 5);
    if (lane == 0) acc += b36;
    if (lane == 1) acc += b37;

    float* red  = h + HSLOT;        // 36 raw bins
    float* red2 = red + 40;         // 36 smoothed bins
    red[lane] = acc;
    if (lane < 4) red[32 + lane] = acc2;
    __syncwarp();

    // Smooth all 36 bins with wrap-padded 5-tap kernel (immediate coefficients).
    float sv = SK0 * red[(lane + 34) % 36];
    sv = fmaf(SK1, red[(lane + 35) % 36], sv);
    sv = fmaf(SK2, red[lane],            sv);
    sv = fmaf(SK1, red[(lane + 1) % 36], sv);
    sv = fmaf(SK0, red[(lane + 2) % 36], sv);
    red2[lane] = sv;
    float sv2 = -1e30f;
    if (lane < 4) {
        int b = 32 + lane;
        sv2 = SK0 * red[(b + 34) % 36];
        sv2 = fmaf(SK1, red[(b + 35) % 36], sv2);
        sv2 = fmaf(SK2, red[b],             sv2);
        sv2 = fmaf(SK1, red[(b + 1) % 36],  sv2);
        sv2 = fmaf(SK0, red[(b + 2) % 36],  sv2);
        red2[b] = sv2;
    }
    __syncwarp();

    // Per-lane candidate: bin `lane`, optionally replaced by bin `32+lane`
    // (strict > keeps lowest-index-wins tie semantics since 32+lane > lane).
    float v = sv;
    int idx = lane;
    if (lane < 4 && sv2 > v) { v = sv2; idx = 32 + lane; }

    // Warp argmax (lowest index on ties, matching jnp.argmax).
#pragma unroll
    for (int off = 16; off; off >>= 1) {
        float v2 = __shfl_xor_sync(FULL, v, off);
        int   i2 = __shfl_xor_sync(FULL, idx, off);
        if (v2 > v || (v2 == v && i2 < idx)) { v = v2; idx = i2; }
    }

    if (lane == 0) {
        float left  = red2[(idx + 35) % 36];
        float right = red2[(idx + 1) % 36];
        float denom = left + right - 2.0f * v;
        float c = 0.5f * (left - right) / denom;
        // angle = pi - (idx + c) * 2*pi/36   (the /HW scale cancels everywhere)
        float angle = 3.14159265358979f - ((float)idx + c) * 0.17453292519943295f;
        out[patch] = angle;
    }
}

// ---------------------------------------------------------------------------
extern "C" void kernel_launch(void* const* d_in, const int* in_sizes, int n_in,
                              void* d_out, int out_size) {
    const float* patch = (const float*)d_in[0];
    float* out = (float*)d_out;
    int n_patches = in_sizes[0] / (PATCH * PATCH);   // 32768

    int blocks = n_patches / WARPS_PER_BLOCK;        // 8192
    patch_orient_kernel<<<blocks, WARPS_PER_BLOCK * 32>>>(patch, out);
}